// round 1
// baseline (speedup 1.0000x reference)
#include <cuda_runtime.h>
#include <math.h>

// ---------------- problem constants ----------------
#define BATCH 4
#define DD 28
#define HH 28
#define WW 8
#define SP (DD*HH*WW)        // 6272 spatial per (b,c)
#define NSP (BATCH*SP)       // 25088
#define CMAX 128

// ---------------- scratch (static device, no allocs) ----------------
__device__ float g_bufA[BATCH*CMAX*SP];   // activations (standard NCDHW)
__device__ float g_bufB[BATCH*CMAX*SP];
__device__ float g_bufT[BATCH*SP*CMAX];   // h3 channel-last for deform gathers
__device__ float g_dwt[27*128*128];       // deform weights as [n][c][o]
__device__ float g_mean[CMAX];
__device__ float g_rstd[CMAX];

// ---------------- direct 3x3x3 conv, pad 1, optional relu ----------------
__global__ void conv3d_kernel(const float* __restrict__ x, const float* __restrict__ wt,
                              const float* __restrict__ bias, float* __restrict__ y,
                              int Cin, int Cout, int relu) {
    int idx = blockIdx.x * blockDim.x + threadIdx.x;
    int total = BATCH * Cout * SP;
    if (idx >= total) return;
    int w = idx & 7;
    int t = idx >> 3;
    int h = t % HH; t /= HH;
    int d = t % DD; t /= DD;
    int o = t % Cout;
    int b = t / Cout;

    float acc = bias[o];
    for (int c = 0; c < Cin; c++) {
        const float* xb = x + ((size_t)(b * Cin + c)) * SP;
        const float* wb = wt + ((size_t)(o * Cin + c)) * 27;
        #pragma unroll
        for (int kd = -1; kd <= 1; kd++) {
            int zd = d + kd; if ((unsigned)zd >= DD) continue;
            #pragma unroll
            for (int kh = -1; kh <= 1; kh++) {
                int zh = h + kh; if ((unsigned)zh >= HH) continue;
                const float* xr = xb + (zd * HH + zh) * WW;
                const float* wr = wb + (kd + 1) * 9 + (kh + 1) * 3;
                #pragma unroll
                for (int kw = -1; kw <= 1; kw++) {
                    int zw = w + kw; if ((unsigned)zw >= WW) continue;
                    acc += xr[zw] * wr[kw + 1];
                }
            }
        }
    }
    if (relu) acc = fmaxf(acc, 0.0f);
    y[idx] = acc;
}

// ---------------- BN stats: one block per channel ----------------
__global__ void bn_stats_kernel(const float* __restrict__ y, int C) {
    int c = blockIdx.x;
    float s = 0.f, sq = 0.f;
    for (int i = threadIdx.x; i < NSP; i += blockDim.x) {
        int b = i / SP, sp = i - b * SP;
        float v = y[((size_t)(b * C + c)) * SP + sp];
        s += v; sq += v * v;
    }
    __shared__ float sh0[256], sh1[256];
    sh0[threadIdx.x] = s; sh1[threadIdx.x] = sq;
    __syncthreads();
    for (int st = 128; st > 0; st >>= 1) {
        if (threadIdx.x < st) {
            sh0[threadIdx.x] += sh0[threadIdx.x + st];
            sh1[threadIdx.x] += sh1[threadIdx.x + st];
        }
        __syncthreads();
    }
    if (threadIdx.x == 0) {
        float m = sh0[0] / (float)NSP;
        float var = sh1[0] / (float)NSP - m * m;
        g_mean[c] = m;
        g_rstd[c] = rsqrtf(var + 1e-5f);
    }
}

// ---------------- BN apply (optionally also writes channel-last copy) ----------------
__global__ void bn_apply_kernel(float* __restrict__ y, const float* __restrict__ gma,
                                const float* __restrict__ bta, int C,
                                float* __restrict__ yt) {
    int idx = blockIdx.x * blockDim.x + threadIdx.x;
    int total = BATCH * C * SP;
    if (idx >= total) return;
    int sp = idx % SP;
    int c = (idx / SP) % C;
    int b = idx / (SP * C);
    float v = (y[idx] - g_mean[c]) * g_rstd[c] * gma[c] + bta[c];
    y[idx] = v;
    if (yt) yt[((size_t)(b * SP + sp)) * CMAX + c] = v;
}

// ---------------- transpose deform weights (O,C,27) -> [n][c][o] ----------------
__global__ void wtrans_kernel(const float* __restrict__ dw) {
    int idx = blockIdx.x * blockDim.x + threadIdx.x;
    int total = 128 * 128 * 27;
    if (idx >= total) return;
    int n = idx % 27;
    int c = (idx / 27) % 128;
    int o = idx / (27 * 128);
    g_dwt[(n * 128 + c) * 128 + o] = dw[idx];
}

// ---------------- deformable conv: 32 spatial positions per block, 128 threads ----------------
__global__ void deform_kernel(const float* __restrict__ ht,   // channel-last h3
                              const float* __restrict__ off,  // (B,81,D,H,W)
                              const float* __restrict__ db,
                              float* __restrict__ y) {
    __shared__ float s_tile[32 * 128];
    __shared__ int   s_qd[32], s_qh[32], s_qw[32];
    __shared__ float s_td[32], s_th[32], s_tw[32];

    int tid = threadIdx.x;       // = channel c for sampling, = output o for GEMV
    int posBase = blockIdx.x * 32;

    float acc[32];
    #pragma unroll
    for (int p = 0; p < 32; p++) acc[p] = 0.f;

    for (int n = 0; n < 27; n++) {
        int kd = n / 9 - 1, kh = (n / 3) % 3 - 1, kw = n % 3 - 1;
        __syncthreads();
        if (tid < 32) {
            int s = posBase + tid;
            int w = s & 7;
            int t = s >> 3;
            int h = t % HH; t /= HH;
            int d = t % DD;
            int b = t / DD;
            size_t obase = (size_t)b * 81 * SP + (size_t)((d * HH + h) * WW + w);
            float od = off[obase + (size_t)n * SP];
            float oh = off[obase + (size_t)(27 + n) * SP];
            float ow_ = off[obase + (size_t)(54 + n) * SP];
            float pd = fminf(fmaxf((float)(d + 1 + kd) + od, 0.f), 29.f);
            float ph = fminf(fmaxf((float)(h + 1 + kh) + oh, 0.f), 29.f);
            float pw = fminf(fmaxf((float)(w + 1 + kw) + ow_, 0.f), 9.f);
            float fd = fminf(fmaxf(floorf(pd), 0.f), 28.f);
            float fh = fminf(fmaxf(floorf(ph), 0.f), 28.f);
            float fw = fminf(fmaxf(floorf(pw), 0.f), 8.f);
            s_qd[tid] = (int)fd; s_td[tid] = fminf(fmaxf(pd - fd, 0.f), 1.f);
            s_qh[tid] = (int)fh; s_th[tid] = fminf(fmaxf(ph - fh, 0.f), 1.f);
            s_qw[tid] = (int)fw; s_tw[tid] = fminf(fmaxf(pw - fw, 0.f), 1.f);
        }
        __syncthreads();

        // sampling: thread = channel, loop positions
        for (int p = 0; p < 32; p++) {
            int s = posBase + p;
            int b = s / SP;
            int qd = s_qd[p], qh = s_qh[p], qw = s_qw[p];
            float td = s_td[p], th = s_th[p], tw = s_tw[p];
            float v = 0.f;
            #pragma unroll
            for (int i = 0; i < 2; i++) {
                int zd = qd + i - 1;                      // orig-coords (padded - 1)
                if ((unsigned)zd >= DD) continue;
                float gd = i ? td : (1.f - td);
                #pragma unroll
                for (int j = 0; j < 2; j++) {
                    int zh = qh + j - 1;
                    if ((unsigned)zh >= HH) continue;
                    float gdh = gd * (j ? th : (1.f - th));
                    #pragma unroll
                    for (int k = 0; k < 2; k++) {
                        int zw = qw + k - 1;
                        if ((unsigned)zw >= WW) continue;
                        float g = gdh * (k ? tw : (1.f - tw));
                        size_t base = (size_t)((b * DD + zd) * HH + zh) * WW + zw;
                        v += g * ht[base * CMAX + tid];
                    }
                }
            }
            s_tile[p * 128 + tid] = v;
        }
        __syncthreads();

        // GEMV: thread = output channel o; coalesced weight reads from g_dwt[n][c][o]
        const float* wrow = g_dwt + (size_t)n * 128 * 128;
        for (int c = 0; c < 128; c++) {
            float wv = wrow[c * 128 + tid];
            const float* st = s_tile + c;
            #pragma unroll 8
            for (int p = 0; p < 32; p++) acc[p] += wv * st[p * 128];
        }
    }

    float bias = db[tid];
    for (int p = 0; p < 32; p++) {
        int s = posBase + p;
        int b = s / SP;
        int sp = s - b * SP;
        y[((size_t)(b * 128 + tid)) * SP + sp] = fmaxf(acc[p] + bias, 0.f);
    }
}

// ---------------- global avg pool + FC + log_softmax ----------------
__global__ void head_kernel(const float* __restrict__ y, const float* __restrict__ fcw,
                            const float* __restrict__ fcb, float* __restrict__ out) {
    int b = blockIdx.x;
    int c = threadIdx.x;   // 128
    const float* p = y + ((size_t)(b * 128 + c)) * SP;
    float s = 0.f;
    for (int i = 0; i < SP; i++) s += p[i];
    __shared__ float pooled[128];
    __shared__ float logits[10];
    pooled[c] = s / (float)SP;
    __syncthreads();
    if (c < 10) {
        float l = fcb[c];
        for (int k = 0; k < 128; k++) l += pooled[k] * fcw[c * 128 + k];
        logits[c] = l;
    }
    __syncthreads();
    if (c == 0) {
        float mx = logits[0];
        for (int j = 1; j < 10; j++) mx = fmaxf(mx, logits[j]);
        float se = 0.f;
        for (int j = 0; j < 10; j++) se += expf(logits[j] - mx);
        float lse = mx + logf(se);
        for (int j = 0; j < 10; j++) out[b * 10 + j] = logits[j] - lse;
    }
}

// ---------------- launcher ----------------
extern "C" void kernel_launch(void* const* d_in, const int* in_sizes, int n_in,
                              void* d_out, int out_size) {
    const float* x   = (const float*)d_in[0];
    const float* c1w = (const float*)d_in[1];  const float* c1b = (const float*)d_in[2];
    const float* g1  = (const float*)d_in[3];  const float* b1  = (const float*)d_in[4];
    const float* c2w = (const float*)d_in[5];  const float* c2b = (const float*)d_in[6];
    const float* g2  = (const float*)d_in[7];  const float* b2  = (const float*)d_in[8];
    const float* c3w = (const float*)d_in[9];  const float* c3b = (const float*)d_in[10];
    const float* g3  = (const float*)d_in[11]; const float* b3  = (const float*)d_in[12];
    const float* ow  = (const float*)d_in[13]; const float* ob  = (const float*)d_in[14];
    const float* dw  = (const float*)d_in[15]; const float* db  = (const float*)d_in[16];
    const float* g4  = (const float*)d_in[17]; const float* b4  = (const float*)d_in[18];
    const float* fcw = (const float*)d_in[19]; const float* fcb = (const float*)d_in[20];

    float* out = (float*)d_out;
    float* offsets = out + BATCH * 10;   // logits first, then offsets (tuple order)

    float *bufA, *bufB, *bufT;
    cudaGetSymbolAddress((void**)&bufA, g_bufA);
    cudaGetSymbolAddress((void**)&bufB, g_bufB);
    cudaGetSymbolAddress((void**)&bufT, g_bufT);

    const int TPB = 256;
    auto grid = [](int total) { return (total + 255) / 256; };

    // layer 1: conv(1->32)+relu, BN
    conv3d_kernel<<<grid(BATCH*32*SP), TPB>>>(x, c1w, c1b, bufA, 1, 32, 1);
    bn_stats_kernel<<<32, 256>>>(bufA, 32);
    bn_apply_kernel<<<grid(BATCH*32*SP), TPB>>>(bufA, g1, b1, 32, nullptr);

    // layer 2: conv(32->64)+relu, BN
    conv3d_kernel<<<grid(BATCH*64*SP), TPB>>>(bufA, c2w, c2b, bufB, 32, 64, 1);
    bn_stats_kernel<<<64, 256>>>(bufB, 64);
    bn_apply_kernel<<<grid(BATCH*64*SP), TPB>>>(bufB, g2, b2, 64, nullptr);

    // layer 3: conv(64->128)+relu, BN (also produce channel-last copy)
    conv3d_kernel<<<grid(BATCH*128*SP), TPB>>>(bufB, c3w, c3b, bufA, 64, 128, 1);
    bn_stats_kernel<<<128, 256>>>(bufA, 128);
    bn_apply_kernel<<<grid(BATCH*128*SP), TPB>>>(bufA, g3, b3, 128, bufT);

    // offsets conv (128->81), no relu, straight into output buffer
    conv3d_kernel<<<grid(BATCH*81*SP), TPB>>>(bufA, ow, ob, offsets, 128, 81, 0);

    // deform conv (128->128) + relu, then BN
    wtrans_kernel<<<grid(128*128*27), TPB>>>(dw);
    deform_kernel<<<NSP / 32, 128>>>(bufT, offsets, db, bufB);
    bn_stats_kernel<<<128, 256>>>(bufB, 128);
    bn_apply_kernel<<<grid(BATCH*128*SP), TPB>>>(bufB, g4, b4, 128, nullptr);

    // pool + fc + log_softmax
    head_kernel<<<BATCH, 128>>>(bufB, fcw, fcb, out);
}

// round 2
// speedup vs baseline: 6.7549x; 6.7549x over previous
#include <cuda_runtime.h>
#include <math.h>

// ---------------- problem constants ----------------
#define BATCH 4
#define DD 28
#define HH 28
#define WW 8
#define SP (DD*HH*WW)        // 6272
#define NSP (BATCH*SP)       // 25088 = 196*128
#define CMAX 128

typedef unsigned long long ull;

// ---------------- packed f32x2 helpers ----------------
__device__ __forceinline__ ull pk(float a, float b) {
    ull r; asm("mov.b64 %0,{%1,%2};" : "=l"(r) : "f"(a), "f"(b)); return r;
}
__device__ __forceinline__ void upk(ull v, float& a, float& b) {
    asm("mov.b64 {%0,%1},%2;" : "=f"(a), "=f"(b) : "l"(v));
}
__device__ __forceinline__ ull ff2(ull a, ull b, ull c) {
    ull d; asm("fma.rn.f32x2 %0,%1,%2,%3;" : "=l"(d) : "l"(a), "l"(b), "l"(c)); return d;
}

// ---------------- scratch (static device, no allocs) ----------------
__device__ float g_bufA[BATCH*SP*CMAX];   // activations channel-last [b][sp][c]
__device__ float g_bufB[BATCH*SP*CMAX];
__device__ float2 g_wpair[1000000];       // all transposed weights, duplicated pairs
__device__ float g_mean[CMAX];
__device__ float g_rstd[CMAX];
__device__ float g_ps[196*CMAX];          // BN partial sums (deterministic)
__device__ float g_pq[196*CMAX];

// weight region offsets (in float2 elements)
#define W1_OFF 0                         // 27*1*32   = 864
#define W2_OFF 864                       // 27*32*64  = 55296
#define W3_OFF 56160                     // 27*64*128 = 221184
#define W4_OFF 277344                    // 27*128*81 = 279936
#define W5_OFF 557280                    // 27*128*128= 442368  (end 999648)

// ---------------- weight transpose: (O,CIN,27) -> pairs [n][ci][o] ----------------
__global__ void wtrans_kernel(const float* __restrict__ w, float2* __restrict__ out,
                              int CIN, int COUT) {
    int idx = blockIdx.x * blockDim.x + threadIdx.x;
    int total = COUT * CIN * 27;
    if (idx >= total) return;
    int n = idx % 27;
    int c = (idx / 27) % CIN;
    int o = idx / (27 * CIN);
    float v = w[idx];
    out[((size_t)n * CIN + c) * COUT + o] = make_float2(v, v);
}

// ---------------- tiled conv3d, channel-last, f32x2 inner ----------------
// block: 128 threads (o), tile: 4h x 8w at fixed d. grid = B*D*(H/4) = 784
template<int CIN, int COUT, bool RELU, bool NCDHW_OUT>
__global__ void conv_cl_kernel(const float* __restrict__ x, const float2* __restrict__ wp,
                               const float* __restrict__ bias, float* __restrict__ y) {
    constexpr int CH = (CIN < 16) ? CIN : 16;
    constexpr int NCH = CIN / CH;
    __shared__ float xs[CH][18][12];   // [ci][zd*6+zh][zw padded 10->12]

    int tid = threadIdx.x;
    int blk = blockIdx.x;
    int hb = blk % 7;
    int d  = (blk / 7) % DD;
    int b  = blk / (7 * DD);
    int h0 = hb * 4;
    int o  = (tid < COUT) ? tid : 0;

    ull acc2[4][4];
    #pragma unroll
    for (int ph = 0; ph < 4; ph++)
        #pragma unroll
        for (int j = 0; j < 4; j++) acc2[ph][j] = 0ull;

    for (int cc = 0; cc < NCH; cc++) {
        __syncthreads();
        // stage input tile (zero-padded halo), coalesced over ci
        for (int i = tid; i < 180 * CH; i += 128) {
            int ci, pos;
            if (CH == 16) { ci = i & 15; pos = i >> 4; }
            else          { ci = i % CH; pos = i / CH; }
            int zw = pos % 10;
            int zh = (pos / 10) % 6;
            int zd = pos / 60;
            int gd = d + zd - 1, gh = h0 + zh - 1, gw = zw - 1;
            float v = 0.0f;
            if ((unsigned)gd < DD && (unsigned)gh < HH && (unsigned)gw < WW)
                v = x[((size_t)((b * DD + gd) * HH + gh) * WW + gw) * CIN + cc * CH + ci];
            xs[ci][zd * 6 + zh][zw] = v;
        }
        __syncthreads();

        for (int ci = 0; ci < CH; ci++) {
            int cglob = cc * CH + ci;
            #pragma unroll
            for (int zd = 0; zd < 3; zd++) {
                #pragma unroll
                for (int zh = 0; zh < 6; zh++) {
                    const float2* row = (const float2*)&xs[ci][zd * 6 + zh][0];
                    float2 e0 = row[0], e1 = row[1], e2 = row[2], e3 = row[3], e4 = row[4];
                    ull P[9];
                    P[0] = pk(e0.x, e0.y); P[2] = pk(e1.x, e1.y); P[4] = pk(e2.x, e2.y);
                    P[6] = pk(e3.x, e3.y); P[8] = pk(e4.x, e4.y);
                    P[1] = pk(e0.y, e1.x); P[3] = pk(e1.y, e2.x);
                    P[5] = pk(e2.y, e3.x); P[7] = pk(e3.y, e4.x);
                    #pragma unroll
                    for (int ph = 0; ph < 4; ph++) {
                        int kh1 = zh - ph;               // kh+1
                        if (kh1 < 0 || kh1 > 2) continue; // constant-folds
                        #pragma unroll
                        for (int kw1 = 0; kw1 < 3; kw1++) {
                            int n = zd * 9 + kh1 * 3 + kw1;
                            ull wv2 = *(const ull*)&wp[((size_t)n * CIN + cglob) * COUT + o];
                            #pragma unroll
                            for (int j = 0; j < 4; j++)
                                acc2[ph][j] = ff2(wv2, P[kw1 + 2 * j], acc2[ph][j]);
                        }
                    }
                }
            }
        }
    }

    if (tid < COUT) {
        float bs = bias[o];
        #pragma unroll
        for (int ph = 0; ph < 4; ph++) {
            #pragma unroll
            for (int j = 0; j < 4; j++) {
                float v0, v1; upk(acc2[ph][j], v0, v1);
                v0 += bs; v1 += bs;
                if (RELU) { v0 = fmaxf(v0, 0.f); v1 = fmaxf(v1, 0.f); }
                int pw = 2 * j;
                if (NCDHW_OUT) {
                    size_t base = (size_t)(b * COUT + o) * SP + (size_t)(d * HH + h0 + ph) * WW;
                    y[base + pw] = v0; y[base + pw + 1] = v1;
                } else {
                    size_t base = ((size_t)((b * DD + d) * HH + (h0 + ph)) * WW + pw) * COUT + o;
                    y[base] = v0; y[base + COUT] = v1;
                }
            }
        }
    }
}

// ---------------- BN: deterministic two-stage stats (channel-last) ----------------
__global__ void bn_part_kernel(const float* __restrict__ y, int C) {
    int blk = blockIdx.x;       // 196 position chunks of 128
    int c = threadIdx.x;
    if (c >= C) return;
    float s = 0.f, q = 0.f;
    int base = blk * 128;
    for (int i = 0; i < 128; i++) {
        float v = y[(size_t)(base + i) * C + c];
        s += v; q += v * v;
    }
    g_ps[blk * CMAX + c] = s;
    g_pq[blk * CMAX + c] = q;
}

__global__ void bn_fin_kernel(int C) {
    int c = threadIdx.x;
    if (c >= C) return;
    float s = 0.f, q = 0.f;
    for (int i = 0; i < 196; i++) { s += g_ps[i * CMAX + c]; q += g_pq[i * CMAX + c]; }
    float m = s / (float)NSP;
    float var = q / (float)NSP - m * m;
    g_mean[c] = m;
    g_rstd[c] = rsqrtf(var + 1e-5f);
}

__global__ void bn_apply_kernel(float* __restrict__ y, const float* __restrict__ gma,
                                const float* __restrict__ bta, int C) {
    int idx = blockIdx.x * blockDim.x + threadIdx.x;
    if (idx >= NSP * C) return;
    int c = idx % C;
    y[idx] = (y[idx] - g_mean[c]) * g_rstd[c] * gma[c] + bta[c];
}

// ---------------- deformable conv (channel-last in/out), f32x2 GEMV ----------------
__global__ void deform_kernel(const float* __restrict__ ht,   // channel-last h3 [pos][128]
                              const float* __restrict__ off,  // (B,81,D,H,W) NCDHW
                              const float2* __restrict__ wp,  // [n][c][o] duplicated pairs
                              const float* __restrict__ db,
                              float* __restrict__ y) {        // channel-last out
    __shared__ float s_tile[128 * 36];     // [c][p], row stride 36 floats (144B)
    __shared__ int   s_qd[32], s_qh[32], s_qw[32];
    __shared__ float s_td[32], s_th[32], s_tw[32];

    int tid = threadIdx.x;
    int posBase = blockIdx.x * 32;

    ull acc2[16];
    #pragma unroll
    for (int j = 0; j < 16; j++) acc2[j] = 0ull;

    for (int n = 0; n < 27; n++) {
        int kd = n / 9 - 1, kh = (n / 3) % 3 - 1, kw = n % 3 - 1;
        __syncthreads();
        if (tid < 32) {
            int s = posBase + tid;
            int w = s & 7;
            int t = s >> 3;
            int h = t % HH; t /= HH;
            int d = t % DD;
            int b = t / DD;
            size_t obase = (size_t)b * 81 * SP + (size_t)((d * HH + h) * WW + w);
            float od  = off[obase + (size_t)n * SP];
            float oh  = off[obase + (size_t)(27 + n) * SP];
            float ow_ = off[obase + (size_t)(54 + n) * SP];
            float pd = fminf(fmaxf((float)(d + 1 + kd) + od, 0.f), 29.f);
            float ph = fminf(fmaxf((float)(h + 1 + kh) + oh, 0.f), 29.f);
            float pw = fminf(fmaxf((float)(w + 1 + kw) + ow_, 0.f), 9.f);
            float fd = fminf(fmaxf(floorf(pd), 0.f), 28.f);
            float fh = fminf(fmaxf(floorf(ph), 0.f), 28.f);
            float fw = fminf(fmaxf(floorf(pw), 0.f), 8.f);
            s_qd[tid] = (int)fd; s_td[tid] = fminf(fmaxf(pd - fd, 0.f), 1.f);
            s_qh[tid] = (int)fh; s_th[tid] = fminf(fmaxf(ph - fh, 0.f), 1.f);
            s_qw[tid] = (int)fw; s_tw[tid] = fminf(fmaxf(pw - fw, 0.f), 1.f);
        }
        __syncthreads();

        // sampling: thread = channel, loop positions (no register arrays indexed by p)
        for (int p = 0; p < 32; p++) {
            int s = posBase + p;
            int b = s / SP;
            int qd = s_qd[p], qh = s_qh[p], qw = s_qw[p];
            float td = s_td[p], th = s_th[p], tw = s_tw[p];
            float v = 0.f;
            #pragma unroll
            for (int i = 0; i < 2; i++) {
                int zd = qd + i - 1;
                if ((unsigned)zd >= DD) continue;
                float gd = i ? td : (1.f - td);
                #pragma unroll
                for (int j = 0; j < 2; j++) {
                    int zh = qh + j - 1;
                    if ((unsigned)zh >= HH) continue;
                    float gdh = gd * (j ? th : (1.f - th));
                    #pragma unroll
                    for (int k = 0; k < 2; k++) {
                        int zw = qw + k - 1;
                        if ((unsigned)zw >= WW) continue;
                        float g = gdh * (k ? tw : (1.f - tw));
                        size_t base = (size_t)((b * DD + zd) * HH + zh) * WW + zw;
                        v += g * ht[base * CMAX + tid];
                    }
                }
            }
            s_tile[tid * 36 + p] = v;
        }
        __syncthreads();

        // GEMV: thread = output channel; fully unrolled over p -> acc stays in regs
        const float2* wrow = wp + (size_t)n * 128 * 128;
        for (int c = 0; c < 128; c++) {
            ull wv2 = *(const ull*)&wrow[c * 128 + tid];
            const ull* st = (const ull*)(s_tile + c * 36);
            #pragma unroll
            for (int j = 0; j < 16; j++)
                acc2[j] = ff2(wv2, st[j], acc2[j]);
        }
    }

    float bs = db[tid];
    #pragma unroll
    for (int j = 0; j < 16; j++) {
        float v0, v1; upk(acc2[j], v0, v1);
        int s0 = posBase + 2 * j;
        y[(size_t)s0 * CMAX + tid]       = fmaxf(v0 + bs, 0.f);
        y[(size_t)(s0 + 1) * CMAX + tid] = fmaxf(v1 + bs, 0.f);
    }
}

// ---------------- global avg pool + FC + log_softmax (channel-last) ----------------
__global__ void head_kernel(const float* __restrict__ y, const float* __restrict__ fcw,
                            const float* __restrict__ fcb, float* __restrict__ out) {
    int b = blockIdx.x;
    int c = threadIdx.x;   // 128
    const float* p = y + (size_t)b * SP * CMAX + c;
    float s = 0.f;
    for (int i = 0; i < SP; i++) s += p[(size_t)i * CMAX];
    __shared__ float pooled[128];
    __shared__ float logits[10];
    pooled[c] = s / (float)SP;
    __syncthreads();
    if (c < 10) {
        float l = fcb[c];
        for (int k = 0; k < 128; k++) l += pooled[k] * fcw[c * 128 + k];
        logits[c] = l;
    }
    __syncthreads();
    if (c == 0) {
        float mx = logits[0];
        for (int j = 1; j < 10; j++) mx = fmaxf(mx, logits[j]);
        float se = 0.f;
        for (int j = 0; j < 10; j++) se += expf(logits[j] - mx);
        float lse = mx + logf(se);
        for (int j = 0; j < 10; j++) out[b * 10 + j] = logits[j] - lse;
    }
}

// ---------------- launcher ----------------
extern "C" void kernel_launch(void* const* d_in, const int* in_sizes, int n_in,
                              void* d_out, int out_size) {
    const float* x   = (const float*)d_in[0];
    const float* c1w = (const float*)d_in[1];  const float* c1b = (const float*)d_in[2];
    const float* g1  = (const float*)d_in[3];  const float* b1  = (const float*)d_in[4];
    const float* c2w = (const float*)d_in[5];  const float* c2b = (const float*)d_in[6];
    const float* g2  = (const float*)d_in[7];  const float* b2  = (const float*)d_in[8];
    const float* c3w = (const float*)d_in[9];  const float* c3b = (const float*)d_in[10];
    const float* g3  = (const float*)d_in[11]; const float* b3  = (const float*)d_in[12];
    const float* ow  = (const float*)d_in[13]; const float* ob  = (const float*)d_in[14];
    const float* dw  = (const float*)d_in[15]; const float* db  = (const float*)d_in[16];
    const float* g4  = (const float*)d_in[17]; const float* b4  = (const float*)d_in[18];
    const float* fcw = (const float*)d_in[19]; const float* fcb = (const float*)d_in[20];

    float* out = (float*)d_out;
    float* offsets = out + BATCH * 10;   // logits first, then offsets (NCDHW)

    float *bufA, *bufB; float2* wpair;
    cudaGetSymbolAddress((void**)&bufA, g_bufA);
    cudaGetSymbolAddress((void**)&bufB, g_bufB);
    cudaGetSymbolAddress((void**)&wpair, g_wpair);

    auto grid = [](int total) { return (total + 255) / 256; };

    // weight transposes (duplicated-pair layout)
    wtrans_kernel<<<grid(32*1*27),    256>>>(c1w, wpair + W1_OFF, 1,   32);
    wtrans_kernel<<<grid(64*32*27),   256>>>(c2w, wpair + W2_OFF, 32,  64);
    wtrans_kernel<<<grid(128*64*27),  256>>>(c3w, wpair + W3_OFF, 64,  128);
    wtrans_kernel<<<grid(81*128*27),  256>>>(ow,  wpair + W4_OFF, 128, 81);
    wtrans_kernel<<<grid(128*128*27), 256>>>(dw,  wpair + W5_OFF, 128, 128);

    const int CBLK = BATCH * DD * (HH / 4);   // 784

    // layer 1: conv(1->32)+relu, BN   (x is NCDHW with C=1 == channel-last)
    conv_cl_kernel<1, 32, true, false><<<CBLK, 128>>>(x, wpair + W1_OFF, c1b, bufA);
    bn_part_kernel<<<196, 128>>>(bufA, 32);
    bn_fin_kernel<<<1, 128>>>(32);
    bn_apply_kernel<<<grid(NSP*32), 256>>>(bufA, g1, b1, 32);

    // layer 2: conv(32->64)+relu, BN
    conv_cl_kernel<32, 64, true, false><<<CBLK, 128>>>(bufA, wpair + W2_OFF, c2b, bufB);
    bn_part_kernel<<<196, 128>>>(bufB, 64);
    bn_fin_kernel<<<1, 128>>>(64);
    bn_apply_kernel<<<grid(NSP*64), 256>>>(bufB, g2, b2, 64);

    // layer 3: conv(64->128)+relu, BN
    conv_cl_kernel<64, 128, true, false><<<CBLK, 128>>>(bufB, wpair + W3_OFF, c3b, bufA);
    bn_part_kernel<<<196, 128>>>(bufA, 128);
    bn_fin_kernel<<<1, 128>>>(128);
    bn_apply_kernel<<<grid(NSP*128), 256>>>(bufA, g3, b3, 128);

    // offsets conv (128->81), no relu, NCDHW straight into output buffer
    conv_cl_kernel<128, 81, false, true><<<CBLK, 128>>>(bufA, wpair + W4_OFF, ob, offsets);

    // deformable conv (128->128) + relu, then BN
    deform_kernel<<<NSP / 32, 128>>>(bufA, offsets, wpair + W5_OFF, db, bufB);
    bn_part_kernel<<<196, 128>>>(bufB, 128);
    bn_fin_kernel<<<1, 128>>>(128);
    bn_apply_kernel<<<grid(NSP*128), 256>>>(bufB, g4, b4, 128);

    // pool + fc + log_softmax
    head_kernel<<<BATCH, 128>>>(bufB, fcw, fcb, out);
}